// round 4
// baseline (speedup 1.0000x reference)
#include <cuda_runtime.h>
#include <math.h>
#include <stdint.h>

#define Bq    8
#define Cc    384
#define Nn    4096
#define HEADS 8
#define HD    48
#define WSZ   (Cc*Cc)          // 147456

// ---------------- scratch (device globals) ----------------
__device__ int8_t g_xs[(size_t)Bq*Nn*Cc];   // spike(x)*4 as int 0..4, [b][n][c]
__device__ int8_t g_q [(size_t)Bq*Nn*Cc];
__device__ int8_t g_k [(size_t)Bq*Nn*Cc];
__device__ int8_t g_v [(size_t)Bq*Nn*Cc];
__device__ int8_t g_a [(size_t)Bq*Nn*Cc];
__device__ int8_t g_w8[4*3*WSZ];            // 4 stages x 3 digits
__device__ float  g_kv[Bq*HEADS*HD*HD];     // raw integer-valued sums
__device__ float  g_s [4*Cc];
__device__ float  g_t [4*Cc];

__device__ __forceinline__ float spikef(float x) {
    return rintf(fminf(fmaxf(x, 0.0f), 4.0f));   // returns k (0..4), round-half-even
}

// ---------------- PTX helpers (plain sm_80-class ISA) ----------------
__device__ __forceinline__ uint32_t smem_u32(const void* p) {
    uint32_t a;
    asm("{ .reg .u64 t; cvta.to.shared.u64 t, %1; cvt.u32.u64 %0, t; }" : "=r"(a) : "l"(p));
    return a;
}
__device__ __forceinline__ void cp16(uint32_t s, const void* g) {
    asm volatile("cp.async.cg.shared.global [%0], [%1], 16;" :: "r"(s), "l"(g));
}
__device__ __forceinline__ void ldsm4(uint32_t* r, uint32_t a) {
    asm volatile("ldmatrix.sync.aligned.m8n8.x4.shared.b16 {%0,%1,%2,%3}, [%4];"
        : "=r"(r[0]), "=r"(r[1]), "=r"(r[2]), "=r"(r[3]) : "r"(a));
}
__device__ __forceinline__ void imma(int* d, const uint32_t* a, const uint32_t* b) {
    asm volatile(
        "mma.sync.aligned.m16n8k32.row.col.s32.s8.s8.s32 "
        "{%0,%1,%2,%3}, {%4,%5,%6,%7}, {%8,%9}, {%0,%1,%2,%3};"
        : "+r"(d[0]), "+r"(d[1]), "+r"(d[2]), "+r"(d[3])
        : "r"(a[0]), "r"(a[1]), "r"(a[2]), "r"(a[3]), "r"(b[0]), "r"(b[1]));
}

// ---------------- small prep kernels ----------------
__global__ void prep_params(const float* __restrict__ gamma, const float* __restrict__ beta,
                            const float* __restrict__ mean,  const float* __restrict__ var,
                            float* __restrict__ s, float* __restrict__ t) {
    int i = threadIdx.x;
    if (i < Cc) {
        float sv = gamma[i] / sqrtf(var[i] + 1e-5f);
        s[i] = sv; t[i] = beta[i] - mean[i] * sv;
    }
}
// 3-digit base-256 signed decomposition of round(W * 2^24)
__global__ void split_w3(const float* __restrict__ w, int8_t* __restrict__ d) {
    int i = blockIdx.x * 256 + threadIdx.x;
    if (i < WSZ) {
        float Mf = rintf(w[i] * 16777216.0f);
        Mf = fminf(fmaxf(Mf, -8355711.0f), 8355711.0f);
        int m = (int)Mf;
        int d0 = ((m + 128) & 255) - 128; m = (m - d0) >> 8;
        int d1 = ((m + 128) & 255) - 128; m = (m - d1) >> 8;
        d[i]           = (int8_t)d0;
        d[WSZ + i]     = (int8_t)d1;
        d[2 * WSZ + i] = (int8_t)m;
    }
}

// ---------------- transpose + spike: x[b][c][n] fp32 -> xs[b][n][c] int8 ----
__global__ __launch_bounds__(256)
void transpose_spike_i8(const float* __restrict__ x, int8_t* __restrict__ xt) {
    __shared__ float tile[64][65];
    const int n0 = blockIdx.x * 64, c0 = blockIdx.y * 64, b = blockIdx.z;
    const int tid = threadIdx.x;
    const float* xb = x + ((size_t)b * Cc + c0) * Nn + n0;
    const int tn = tid & 63, tg = tid >> 6;
    #pragma unroll
    for (int i = 0; i < 16; ++i)
        tile[tg * 16 + i][tn] = xb[(size_t)(tg * 16 + i) * Nn + tn];
    __syncthreads();
    int8_t* yb = xt + (size_t)b * Nn * Cc;
    #pragma unroll
    for (int p = 0; p < 4; ++p) {
        int idx = tid + p * 256;
        int n = idx >> 4, cw = idx & 15;
        uint32_t pk = 0;
        #pragma unroll
        for (int k = 0; k < 4; ++k)
            pk |= ((uint32_t)(int)spikef(tile[cw * 4 + k][n])) << (k * 8);
        *reinterpret_cast<uint32_t*>(yb + (size_t)(n0 + n) * Cc + c0 + cw * 4) = pk;
    }
}

// ---------------- IMMA GEMM: Y = BN(W @ X/4) [+spike] ------------------------
// A: 3 digit planes [m][k] int8.  B: X [n][c=k] int8 (values 0..4).
// Block 128m x 64n, 8 warps (4m x 2n), warp 32x32, k-chunk 32, double buffer.
// smem per stage: 3 digit planes (2 k-halves x 128 m x 16B) + B (2 x 64 x 16B)
#define STG 14336

__global__ __launch_bounds__(256)
void gemm_imma(const int8_t* __restrict__ Wd, const int8_t* __restrict__ X,
               void* __restrict__ Y, const float* __restrict__ sArr,
               const float* __restrict__ tArr, int mode)
{
    __shared__ char smem[2 * STG];
    const uint32_t sb = smem_u32(smem);
    const int tid = threadIdx.x, lane = tid & 31, wid = tid >> 5;
    const int wm = wid >> 1, wn = wid & 1;
    const int n0 = blockIdx.x * 64, m0 = blockIdx.y * 128, b = blockIdx.z;
    const int8_t* Xb = X + (size_t)b * Nn * Cc;

    int acc[3][2][4][4];
    #pragma unroll
    for (int d = 0; d < 3; ++d)
        #pragma unroll
        for (int t = 0; t < 2; ++t)
            #pragma unroll
            for (int j = 0; j < 4; ++j)
                #pragma unroll
                for (int e = 0; e < 4; ++e) acc[d][t][j][e] = 0;

    auto load_chunk = [&](int kc, int st) {
        int m = tid >> 1, kh = tid & 1;
        const int8_t* wp = Wd + (size_t)(m0 + m) * Cc + kc * 32 + kh * 16;
        uint32_t da = sb + st * STG + kh * 2048 + m * 16;
        cp16(da,        wp);
        cp16(da + 4096, wp + WSZ);
        cp16(da + 8192, wp + 2 * WSZ);
        if (tid < 128) {
            int n = tid >> 1, k2 = tid & 1;
            cp16(sb + st * STG + 12288 + k2 * 1024 + n * 16,
                 Xb + (size_t)(n0 + n) * Cc + kc * 32 + k2 * 16);
        }
        asm volatile("cp.async.commit_group;");
    };

    load_chunk(0, 0);

    const int mat = lane >> 3;
    const uint32_t a_row16 = (uint32_t)(wm * 32 + (lane & 7) + ((mat & 1) << 3)) * 16
                             + (uint32_t)(mat >> 1) * 2048;
    const uint32_t b_off   = 12288 + (uint32_t)(mat & 1) * 1024
                             + (uint32_t)(wn * 32 + (lane & 7) + ((mat >> 1) << 3)) * 16;

    for (int kc = 0; kc < 12; ++kc) {
        if (kc + 1 < 12) {
            load_chunk(kc + 1, (kc + 1) & 1);
            asm volatile("cp.async.wait_group 1;");
        } else {
            asm volatile("cp.async.wait_group 0;");
        }
        __syncthreads();

        uint32_t base = sb + (kc & 1) * STG;

        uint32_t B[2][4];
        ldsm4(B[0], base + b_off);
        ldsm4(B[1], base + b_off + 256);       // g=1: +16 n rows * 16B
        #pragma unroll
        for (int d = 0; d < 3; ++d) {
            #pragma unroll
            for (int t = 0; t < 2; ++t) {
                uint32_t A[4];
                ldsm4(A, base + d * 4096 + a_row16 + (uint32_t)t * 256);
                #pragma unroll
                for (int j = 0; j < 4; ++j)
                    imma(acc[d][t][j], A, &B[j >> 1][(j & 1) * 2]);
            }
        }
        __syncthreads();
    }

    const float C0 = 1.4901161193847656e-8f;   // 2^-26
    const float C1 = 3.814697265625e-6f;       // 2^-18
    const float C2 = 9.765625e-4f;             // 2^-10

    if (mode == 0) {
        // BN + spike -> int8 (k value), restage [n64][c128] then coalesced out
        #pragma unroll
        for (int t = 0; t < 2; ++t) {
            int r0 = wm * 32 + t * 16 + (lane >> 2);
            int r1 = r0 + 8;
            float s0 = sArr[m0 + r0], t0 = tArr[m0 + r0];
            float s1 = sArr[m0 + r1], t1 = tArr[m0 + r1];
            #pragma unroll
            for (int j = 0; j < 4; ++j) {
                int nc = wn * 32 + j * 8 + 2 * (lane & 3);
                #pragma unroll
                for (int e = 0; e < 4; ++e) {
                    float y = fmaf((float)acc[2][t][j][e], C2,
                              fmaf((float)acc[1][t][j][e], C1,
                                   (float)acc[0][t][j][e] * C0));
                    float ss = (e < 2) ? s0 : s1, tt = (e < 2) ? t0 : t1;
                    int   row = (e < 2) ? r0 : r1;
                    int   nel = nc + (e & 1);
                    smem[nel * 128 + row] = (char)(int)spikef(fmaf(y, ss, tt));
                }
            }
        }
        __syncthreads();
        int8_t* Yb = (int8_t*)Y + (size_t)b * Nn * Cc;
        #pragma unroll
        for (int p = 0; p < 2; ++p) {
            int idx = tid + p * 256;
            int n = idx >> 3, q = idx & 7;
            uint4 u = *reinterpret_cast<const uint4*>(smem + n * 128 + q * 16);
            *reinterpret_cast<uint4*>(Yb + (size_t)(n0 + n) * Cc + m0 + q * 16) = u;
        }
    } else {
        // BN only -> fp32 [c][n] direct (final output)
        float* Yb = (float*)Y + (size_t)b * (Cc * Nn);
        #pragma unroll
        for (int t = 0; t < 2; ++t) {
            int r0 = wm * 32 + t * 16 + (lane >> 2);
            int r1 = r0 + 8;
            float s0 = sArr[m0 + r0], t0 = tArr[m0 + r0];
            float s1 = sArr[m0 + r1], t1 = tArr[m0 + r1];
            #pragma unroll
            for (int j = 0; j < 4; ++j) {
                int nc = n0 + wn * 32 + j * 8 + 2 * (lane & 3);
                float y0 = fmaf((float)acc[2][t][j][0], C2, fmaf((float)acc[1][t][j][0], C1, (float)acc[0][t][j][0] * C0));
                float y1 = fmaf((float)acc[2][t][j][1], C2, fmaf((float)acc[1][t][j][1], C1, (float)acc[0][t][j][1] * C0));
                float y2 = fmaf((float)acc[2][t][j][2], C2, fmaf((float)acc[1][t][j][2], C1, (float)acc[0][t][j][2] * C0));
                float y3 = fmaf((float)acc[2][t][j][3], C2, fmaf((float)acc[1][t][j][3], C1, (float)acc[0][t][j][3] * C0));
                float2 p0 = make_float2(fmaf(y0, s0, t0), fmaf(y1, s0, t0));
                float2 p1 = make_float2(fmaf(y2, s1, t1), fmaf(y3, s1, t1));
                *reinterpret_cast<float2*>(Yb + (size_t)(m0 + r0) * Nn + nc) = p0;
                *reinterpret_cast<float2*>(Yb + (size_t)(m0 + r1) * Nn + nc) = p1;
            }
        }
    }
}

// ---------------- kv (raw): kv[b,h,d,e] = sum_n kq[n,d]*kq_v[n,e] -----------
__global__ void zero_kv_kernel() {
    int i = blockIdx.x * blockDim.x + threadIdx.x;
    if (i < Bq * HEADS * HD * HD) g_kv[i] = 0.0f;
}
__global__ __launch_bounds__(256)
void kv_kernel() {
    const int chunk = blockIdx.x, h = blockIdx.y, b = blockIdx.z;
    const int n0 = chunk * 512;
    const int8_t* kp = g_k + (size_t)b * Nn * Cc + h * HD;
    const int8_t* vp = g_v + (size_t)b * Nn * Cc + h * HD;

    __shared__ float ks[HD][64];
    __shared__ float vs[HD][64];

    const int tid = threadIdx.x;
    const int te = tid & 15, td = tid >> 4;
    float acc[3][3] = {};

    for (int nt = 0; nt < 512; nt += 64) {
        #pragma unroll
        for (int p = 0; p < 3; ++p) {
            int idx = tid + p * 256;
            int n = idx / 12, w = idx % 12;
            size_t row = (size_t)(n0 + nt + n) * Cc;
            uint32_t uk = *reinterpret_cast<const uint32_t*>(kp + row + w * 4);
            uint32_t uv = *reinterpret_cast<const uint32_t*>(vp + row + w * 4);
            #pragma unroll
            for (int z = 0; z < 4; ++z) {
                ks[w * 4 + z][n] = (float)((uk >> (z * 8)) & 255);
                vs[w * 4 + z][n] = (float)((uv >> (z * 8)) & 255);
            }
        }
        __syncthreads();
        #pragma unroll 4
        for (int n = 0; n < 64; ++n) {
            float kd[3], ve[3];
            #pragma unroll
            for (int i = 0; i < 3; ++i) kd[i] = ks[td * 3 + i][n];
            #pragma unroll
            for (int i = 0; i < 3; ++i) ve[i] = vs[te * 3 + i][n];
            #pragma unroll
            for (int i = 0; i < 3; ++i)
                #pragma unroll
                for (int j = 0; j < 3; ++j)
                    acc[i][j] = fmaf(kd[i], ve[j], acc[i][j]);
        }
        __syncthreads();
    }
    float* kvp = g_kv + (size_t)(b * HEADS + h) * HD * HD;
    #pragma unroll
    for (int i = 0; i < 3; ++i)
        #pragma unroll
        for (int j = 0; j < 3; ++j)
            atomicAdd(&kvp[(td * 3 + i) * HD + te * 3 + j], acc[i][j]);
}

// ---------------- attn: a[n][h*48+e] = spike((sum_d kq_d*kvraw)/64 * mult) ---
__global__ __launch_bounds__(256)
void attn_kernel() {
    const int h = blockIdx.y, b = blockIdx.z;
    const int tid = threadIdx.x;
    const int n = blockIdx.x * 256 + tid;

    __shared__ float4 kv4[HD][12];
    __shared__ uint32_t outb[256][12];
    const float* kvp = g_kv + (size_t)(b * HEADS + h) * HD * HD;
    for (int i = tid; i < HD * 12; i += 256)
        reinterpret_cast<float4*>(kv4)[i] = reinterpret_cast<const float4*>(kvp)[i];
    __syncthreads();

    const int8_t* qp = g_q + ((size_t)b * Nn + n) * Cc + h * HD;
    float qr[HD];
    #pragma unroll
    for (int i = 0; i < 12; ++i) {
        uint32_t u = reinterpret_cast<const uint32_t*>(qp)[i];
        #pragma unroll
        for (int z = 0; z < 4; ++z) qr[i * 4 + z] = (float)((u >> (z * 8)) & 255);
    }

    float4 accv[12];
    #pragma unroll
    for (int e = 0; e < 12; ++e) accv[e] = make_float4(0.f, 0.f, 0.f, 0.f);
    #pragma unroll
    for (int d = 0; d < HD; ++d) {
        float qd = qr[d];
        #pragma unroll
        for (int e = 0; e < 12; ++e) {
            float4 kk = kv4[d][e];
            accv[e].x = fmaf(qd, kk.x, accv[e].x);
            accv[e].y = fmaf(qd, kk.y, accv[e].y);
            accv[e].z = fmaf(qd, kk.z, accv[e].z);
            accv[e].w = fmaf(qd, kk.w, accv[e].w);
        }
    }

    const float mult = 0.28867513459481287f;   // fp32(2/sqrt(48))
    const float inv64 = 0.015625f;
    #pragma unroll
    for (int e = 0; e < 12; ++e) {
        uint32_t pk = 0;
        pk |= (uint32_t)(int)spikef((accv[e].x * inv64) * mult);
        pk |= (uint32_t)(int)spikef((accv[e].y * inv64) * mult) << 8;
        pk |= (uint32_t)(int)spikef((accv[e].z * inv64) * mult) << 16;
        pk |= (uint32_t)(int)spikef((accv[e].w * inv64) * mult) << 24;
        outb[tid][e] = pk;
    }
    __syncthreads();

    int8_t* ab = g_a + (size_t)b * Nn * Cc + (size_t)blockIdx.x * 256 * Cc + h * HD;
    #pragma unroll
    for (int p = 0; p < 12; ++p) {
        int idx = tid + p * 256;
        int nl = idx / 12, w = idx % 12;
        *reinterpret_cast<uint32_t*>(ab + (size_t)nl * Cc + w * 4) = outb[nl][w];
    }
}

// ---------------- launch ----------------
extern "C" void kernel_launch(void* const* d_in, const int* in_sizes, int n_in,
                              void* d_out, int out_size) {
    const float* x = (const float*)d_in[0];
    int8_t *xs, *qb, *kb, *vb, *ab, *w8;
    float *sarr, *tarr;
    cudaGetSymbolAddress((void**)&xs, g_xs);
    cudaGetSymbolAddress((void**)&qb, g_q);
    cudaGetSymbolAddress((void**)&kb, g_k);
    cudaGetSymbolAddress((void**)&vb, g_v);
    cudaGetSymbolAddress((void**)&ab, g_a);
    cudaGetSymbolAddress((void**)&w8, g_w8);
    cudaGetSymbolAddress((void**)&sarr, g_s);
    cudaGetSymbolAddress((void**)&tarr, g_t);

    for (int p = 0; p < 4; ++p) {
        prep_params<<<1, 384>>>((const float*)d_in[2 + p * 5], (const float*)d_in[3 + p * 5],
                                (const float*)d_in[4 + p * 5], (const float*)d_in[5 + p * 5],
                                sarr + p * Cc, tarr + p * Cc);
        split_w3<<<(WSZ + 255) / 256, 256>>>((const float*)d_in[1 + p * 5], w8 + p * 3 * WSZ);
    }

    transpose_spike_i8<<<dim3(Nn / 64, Cc / 64, Bq), 256>>>(x, xs);

    dim3 gg(Nn / 64, Cc / 128, Bq);
    gemm_imma<<<gg, 256>>>(w8 + 0 * 3 * WSZ, xs, qb, sarr + 0 * Cc, tarr + 0 * Cc, 0);
    gemm_imma<<<gg, 256>>>(w8 + 1 * 3 * WSZ, xs, kb, sarr + 1 * Cc, tarr + 1 * Cc, 0);
    gemm_imma<<<gg, 256>>>(w8 + 2 * 3 * WSZ, xs, vb, sarr + 2 * Cc, tarr + 2 * Cc, 0);

    zero_kv_kernel<<<(Bq * HEADS * HD * HD + 255) / 256, 256>>>();
    kv_kernel<<<dim3(8, HEADS, Bq), 256>>>();
    attn_kernel<<<dim3(Nn / 256, HEADS, Bq), 256>>>();

    gemm_imma<<<gg, 256>>>(w8 + 3 * 3 * WSZ, ab, d_out, sarr + 3 * Cc, tarr + 3 * Cc, 1);
}

// round 5
// speedup vs baseline: 3.5910x; 3.5910x over previous
#include <cuda_runtime.h>
#include <cuda_bf16.h>
#include <math.h>
#include <stdint.h>

#define Bq    8
#define Cc    384
#define Nn    4096
#define HEADS 8
#define HD    48
#define WSZ   (Cc*Cc)

// ---------------- scratch (device globals) ----------------
__device__ __nv_bfloat16 g_xs[(size_t)Bq*Cc*Nn];   // spike(x)  [b][c][n]
__device__ __nv_bfloat16 g_q [(size_t)Bq*Cc*Nn];
__device__ __nv_bfloat16 g_k [(size_t)Bq*Cc*Nn];
__device__ __nv_bfloat16 g_v [(size_t)Bq*Cc*Nn];
__device__ __nv_bfloat16 g_a [(size_t)Bq*Cc*Nn];
__device__ __nv_bfloat16 g_whi[4*WSZ];             // stacked rows: [1536][384]
__device__ __nv_bfloat16 g_wlo[4*WSZ];
__device__ float g_kv[Bq*HEADS*HD*HD];
__device__ float g_s [4*Cc];                       // stacked: index = global m row
__device__ float g_t [4*Cc];

__device__ __forceinline__ float spikef(float x) {
    return rintf(fminf(fmaxf(x, 0.0f), 4.0f)) * 0.25f;
}

// ---------------- PTX helpers (sm_80-class ISA, compiles on plain sm_103) ----
__device__ __forceinline__ uint32_t smem_u32(const void* p) {
    uint32_t a;
    asm("{ .reg .u64 t; cvta.to.shared.u64 t, %1; cvt.u32.u64 %0, t; }" : "=r"(a) : "l"(p));
    return a;
}
__device__ __forceinline__ void cp16(uint32_t s, const void* g) {
    asm volatile("cp.async.cg.shared.global [%0], [%1], 16;" :: "r"(s), "l"(g));
}
__device__ __forceinline__ void ldsm4(uint32_t* r, uint32_t a) {
    asm volatile("ldmatrix.sync.aligned.m8n8.x4.shared.b16 {%0,%1,%2,%3}, [%4];"
        : "=r"(r[0]), "=r"(r[1]), "=r"(r[2]), "=r"(r[3]) : "r"(a));
}
__device__ __forceinline__ void ldsm4t(uint32_t* r, uint32_t a) {
    asm volatile("ldmatrix.sync.aligned.m8n8.x4.trans.shared.b16 {%0,%1,%2,%3}, [%4];"
        : "=r"(r[0]), "=r"(r[1]), "=r"(r[2]), "=r"(r[3]) : "r"(a));
}
__device__ __forceinline__ void mma16816(float* d, const uint32_t* a, const uint32_t* b) {
    asm volatile(
        "mma.sync.aligned.m16n8k16.row.col.f32.bf16.bf16.f32 "
        "{%0,%1,%2,%3}, {%4,%5,%6,%7}, {%8,%9}, {%0,%1,%2,%3};"
        : "+f"(d[0]), "+f"(d[1]), "+f"(d[2]), "+f"(d[3])
        : "r"(a[0]), "r"(a[1]), "r"(a[2]), "r"(a[3]), "r"(b[0]), "r"(b[1]));
}

// ---------------- small prep kernels ----------------
__global__ void prep_params(const float* __restrict__ gamma, const float* __restrict__ beta,
                            const float* __restrict__ mean,  const float* __restrict__ var,
                            float* __restrict__ s, float* __restrict__ t) {
    int i = threadIdx.x;
    if (i < Cc) {
        float sv = gamma[i] / sqrtf(var[i] + 1e-5f);
        s[i] = sv; t[i] = beta[i] - mean[i] * sv;
    }
}
__global__ void split_w(const float* __restrict__ w, __nv_bfloat16* __restrict__ hi,
                        __nv_bfloat16* __restrict__ lo) {
    int i = blockIdx.x * 256 + threadIdx.x;
    if (i < WSZ) {
        float v = w[i];
        __nv_bfloat16 h = __float2bfloat16(v);
        hi[i] = h;
        lo[i] = __float2bfloat16(v - __bfloat162float(h));
    }
}
__global__ void spike_x_kernel(const float* __restrict__ x, __nv_bfloat16* __restrict__ y, int n4) {
    int i = blockIdx.x * 256 + threadIdx.x;
    if (i < n4) {
        float4 v = reinterpret_cast<const float4*>(x)[i];
        __nv_bfloat162 a = __floats2bfloat162_rn(spikef(v.x), spikef(v.y));
        __nv_bfloat162 b = __floats2bfloat162_rn(spikef(v.z), spikef(v.w));
        uint2 pk;
        pk.x = *reinterpret_cast<uint32_t*>(&a);
        pk.y = *reinterpret_cast<uint32_t*>(&b);
        reinterpret_cast<uint2*>(y)[i] = pk;
    }
}

// ---------------- HMMA GEMM, block 128m x 256n, warp 64x64, k-chunk 32 -------
// A = stacked W rows [1536][384] (hi+lo planes); B = X [k][n] via ldsm.trans.
// mode 0: spike(BN(.)) -> bf16 [c][n] into q/k/v by stage (m0/384)
// mode 1: BN(.) -> fp32 [c][n] direct (final output)
#define STG_B 32768            // per stage: A_hi 8K | A_lo 8K | B 16K
#define SMEM_GEMM 65536

__global__ __launch_bounds__(256)
void gemm_hmma(const __nv_bfloat16* __restrict__ Whi, const __nv_bfloat16* __restrict__ Wlo,
               const __nv_bfloat16* __restrict__ X,
               __nv_bfloat16* __restrict__ oq, __nv_bfloat16* __restrict__ ok,
               __nv_bfloat16* __restrict__ ov, float* __restrict__ ofp,
               const float* __restrict__ sArr, const float* __restrict__ tArr,
               int mbase, int mode)
{
    extern __shared__ char smem[];
    const uint32_t sb = smem_u32(smem);
    const int tid = threadIdx.x, lane = tid & 31, wid = tid >> 5;
    const int wm = wid & 1, wn = wid >> 1;             // 2 m-halves x 4 n-quarters
    const int n0 = blockIdx.x * 256, m0 = mbase + blockIdx.y * 128, b = blockIdx.z;
    const __nv_bfloat16* Xb = X + (size_t)b * (Cc * Nn);

    float acc[4][8][4];
    #pragma unroll
    for (int t = 0; t < 4; ++t)
        #pragma unroll
        for (int j = 0; j < 8; ++j)
            #pragma unroll
            for (int e = 0; e < 4; ++e) acc[t][j][e] = 0.0f;

    auto load_chunk = [&](int kc, int st) {
        uint32_t base = sb + st * STG_B;
        #pragma unroll
        for (int p = 0; p < 2; ++p) {                   // A: 128 rows x 4 c-chunks
            int idx = tid + p * 256;
            int row = idx >> 2, c = idx & 3;
            uint32_t so = row * 64 + ((c ^ ((row >> 1) & 3)) << 4);
            const __nv_bfloat16* gp = Whi + (size_t)(m0 + row) * Cc + kc * 32 + c * 8;
            cp16(base + so, gp);
            cp16(base + 8192 + so, Wlo + (size_t)(m0 + row) * Cc + kc * 32 + c * 8);
        }
        #pragma unroll
        for (int p = 0; p < 4; ++p) {                   // B: 32 k-rows x 32 c-chunks
            int idx = tid + p * 256;
            int kr = idx >> 5, c = idx & 31;
            uint32_t so = kr * 512 + (((c & 24) | ((c & 7) ^ (kr & 7))) << 4);
            cp16(base + 16384 + so, Xb + (size_t)(kc * 32 + kr) * Nn + n0 + c * 8);
        }
        asm volatile("cp.async.commit_group;");
    };

    load_chunk(0, 0);

    const int sel = lane >> 3, l7 = lane & 7;

    for (int kc = 0; kc < 12; ++kc) {
        if (kc + 1 < 12) {
            load_chunk(kc + 1, (kc + 1) & 1);
            asm volatile("cp.async.wait_group 1;");
        } else {
            asm volatile("cp.async.wait_group 0;");
        }
        __syncthreads();

        uint32_t base = sb + (kc & 1) * STG_B;

        #pragma unroll
        for (int h = 0; h < 2; ++h) {
            uint32_t ahi[4][4], alo[4][4], bb[4][4];
            #pragma unroll
            for (int t = 0; t < 4; ++t) {
                int row = wm * 64 + t * 16 + (sel & 1) * 8 + l7;
                int kcx = h * 2 + (sel >> 1);
                uint32_t ad = base + row * 64 + ((kcx ^ ((row >> 1) & 3)) << 4);
                ldsm4(ahi[t], ad);
                ldsm4(alo[t], ad + 8192);
            }
            #pragma unroll
            for (int j = 0; j < 4; ++j) {
                int kr = h * 16 + (sel & 1) * 8 + l7;
                int nc = (wn * 64 + j * 16 + (sel >> 1) * 8) >> 3;
                uint32_t bd = base + 16384 + kr * 512 +
                              (((nc & 24) | ((nc & 7) ^ (kr & 7))) << 4);
                ldsm4t(bb[j], bd);
            }
            #pragma unroll
            for (int t = 0; t < 4; ++t)
                #pragma unroll
                for (int j = 0; j < 8; ++j) {
                    const uint32_t* bf = &bb[j >> 1][(j & 1) * 2];
                    mma16816(acc[t][j], ahi[t], bf);
                    mma16816(acc[t][j], alo[t], bf);
                }
        }
        __syncthreads();
    }

    if (mode == 0) {
        // BN + spike -> bf16 [c][n]; two passes over 128-col halves via smem
        const int st = m0 / Cc;
        __nv_bfloat16* Yb = (st == 0 ? oq : st == 1 ? ok : ov) + (size_t)b * (Cc * Nn);
        const int mloc = m0 - st * Cc;
        __nv_bfloat16* sm = reinterpret_cast<__nv_bfloat16*>(smem);
        #pragma unroll
        for (int p = 0; p < 2; ++p) {
            if ((wn >> 1) == p) {
                #pragma unroll
                for (int t = 0; t < 4; ++t) {
                    int r0 = wm * 64 + t * 16 + (lane >> 2);
                    float s0 = sArr[m0 + r0], t0 = tArr[m0 + r0];
                    float s1 = sArr[m0 + r0 + 8], t1 = tArr[m0 + r0 + 8];
                    #pragma unroll
                    for (int j = 0; j < 8; ++j) {
                        int col = (wn & 1) * 64 + j * 8 + 2 * (lane & 3);
                        __nv_bfloat162 p0 = __floats2bfloat162_rn(
                            spikef(acc[t][j][0] * s0 + t0), spikef(acc[t][j][1] * s0 + t0));
                        __nv_bfloat162 p1 = __floats2bfloat162_rn(
                            spikef(acc[t][j][2] * s1 + t1), spikef(acc[t][j][3] * s1 + t1));
                        *reinterpret_cast<__nv_bfloat162*>(sm + r0 * 136 + col) = p0;
                        *reinterpret_cast<__nv_bfloat162*>(sm + (r0 + 8) * 136 + col) = p1;
                    }
                }
            }
            __syncthreads();
            #pragma unroll
            for (int it = 0; it < 8; ++it) {
                int idx = tid + it * 256;
                int row = idx >> 4, ci = idx & 15;
                uint4 u4 = *reinterpret_cast<const uint4*>(sm + row * 136 + ci * 8);
                *reinterpret_cast<uint4*>(
                    Yb + (size_t)(mloc + row) * Nn + n0 + p * 128 + ci * 8) = u4;
            }
            __syncthreads();
        }
    } else {
        // BN only -> fp32 [c][n] direct (final output)
        float* Yb = ofp + (size_t)b * (Cc * Nn);
        const int mloc = m0 - 3 * Cc;
        #pragma unroll
        for (int t = 0; t < 4; ++t) {
            int r0 = wm * 64 + t * 16 + (lane >> 2);
            float s0 = sArr[m0 + r0], t0 = tArr[m0 + r0];
            float s1 = sArr[m0 + r0 + 8], t1 = tArr[m0 + r0 + 8];
            #pragma unroll
            for (int j = 0; j < 8; ++j) {
                int col = n0 + wn * 64 + j * 8 + 2 * (lane & 3);
                float2 p0 = make_float2(acc[t][j][0] * s0 + t0, acc[t][j][1] * s0 + t0);
                float2 p1 = make_float2(acc[t][j][2] * s1 + t1, acc[t][j][3] * s1 + t1);
                *reinterpret_cast<float2*>(Yb + (size_t)(mloc + r0) * Nn + col) = p0;
                *reinterpret_cast<float2*>(Yb + (size_t)(mloc + r0 + 8) * Nn + col) = p1;
            }
        }
    }
}

// ---------------- kv: kv[b,h,d,e] = sum_n k[d,n]*v[e,n] (exact fp32 atomics) --
__global__ void zero_kv_kernel() {
    int i = blockIdx.x * blockDim.x + threadIdx.x;
    if (i < Bq * HEADS * HD * HD) g_kv[i] = 0.0f;
}
__global__ __launch_bounds__(256)
void kv_kernel() {
    const int chunk = blockIdx.x, h = blockIdx.y, b = blockIdx.z;
    const int n0 = chunk * 512;
    const __nv_bfloat16* kp = g_k + ((size_t)b * Cc + h * HD) * Nn;
    const __nv_bfloat16* vp = g_v + ((size_t)b * Cc + h * HD) * Nn;

    __shared__ float ks[HD][65];
    __shared__ float vs[HD][65];

    const int tid = threadIdx.x;
    const int te = tid & 15, td = tid >> 4;
    float acc[3][3] = {};

    for (int nt = 0; nt < 512; nt += 64) {
        for (int i = tid; i < HD * 64; i += 256) {
            int r = i >> 6, c = i & 63;
            ks[r][c] = __bfloat162float(kp[(size_t)r * Nn + n0 + nt + c]);
            vs[r][c] = __bfloat162float(vp[(size_t)r * Nn + n0 + nt + c]);
        }
        __syncthreads();
        #pragma unroll 4
        for (int n = 0; n < 64; ++n) {
            float kd[3], ve[3];
            #pragma unroll
            for (int i = 0; i < 3; ++i) kd[i] = ks[td * 3 + i][n];
            #pragma unroll
            for (int i = 0; i < 3; ++i) ve[i] = vs[te * 3 + i][n];
            #pragma unroll
            for (int i = 0; i < 3; ++i)
                #pragma unroll
                for (int j = 0; j < 3; ++j)
                    acc[i][j] = fmaf(kd[i], ve[j], acc[i][j]);
        }
        __syncthreads();
    }
    float* kvp = g_kv + (size_t)(b * HEADS + h) * HD * HD;
    #pragma unroll
    for (int i = 0; i < 3; ++i)
        #pragma unroll
        for (int j = 0; j < 3; ++j)
            atomicAdd(&kvp[(td * 3 + i) * HD + te * 3 + j], acc[i][j]);
}

// ---------------- attn: a[h*48+e, n] = spike(mult * sum_d q[d,n]*kv[d,e]) ----
__global__ __launch_bounds__(256)
void attn_kernel() {
    const int n = blockIdx.x * 256 + threadIdx.x;
    const int h = blockIdx.y, b = blockIdx.z;

    __shared__ float4 kv4[HD][12];
    const float* kvp = g_kv + (size_t)(b * HEADS + h) * HD * HD;
    for (int i = threadIdx.x; i < HD * 12; i += 256)
        reinterpret_cast<float4*>(kv4)[i] = reinterpret_cast<const float4*>(kvp)[i];
    __syncthreads();

    const __nv_bfloat16* qp = g_q + ((size_t)b * Cc + h * HD) * Nn + n;
    float qr[HD];
    #pragma unroll
    for (int d = 0; d < HD; ++d) qr[d] = __bfloat162float(qp[(size_t)d * Nn]);

    float4 accv[12];
    #pragma unroll
    for (int e = 0; e < 12; ++e) accv[e] = make_float4(0.f, 0.f, 0.f, 0.f);
    #pragma unroll
    for (int d = 0; d < HD; ++d) {
        float qd = qr[d];
        #pragma unroll
        for (int e = 0; e < 12; ++e) {
            float4 kk = kv4[d][e];
            accv[e].x = fmaf(qd, kk.x, accv[e].x);
            accv[e].y = fmaf(qd, kk.y, accv[e].y);
            accv[e].z = fmaf(qd, kk.z, accv[e].z);
            accv[e].w = fmaf(qd, kk.w, accv[e].w);
        }
    }

    __nv_bfloat16* ap = g_a + ((size_t)b * Cc + h * HD) * Nn + n;
    const float mult = 0.28867513459481287f;   // 2 / sqrt(48)
    #pragma unroll
    for (int e = 0; e < 12; ++e) {
        ap[(size_t)(e * 4 + 0) * Nn] = __float2bfloat16(spikef(accv[e].x * mult));
        ap[(size_t)(e * 4 + 1) * Nn] = __float2bfloat16(spikef(accv[e].y * mult));
        ap[(size_t)(e * 4 + 2) * Nn] = __float2bfloat16(spikef(accv[e].z * mult));
        ap[(size_t)(e * 4 + 3) * Nn] = __float2bfloat16(spikef(accv[e].w * mult));
    }
}

// ---------------- launch ----------------
extern "C" void kernel_launch(void* const* d_in, const int* in_sizes, int n_in,
                              void* d_out, int out_size) {
    const float* x = (const float*)d_in[0];
    __nv_bfloat16 *xs, *qb, *kb, *vb, *ab, *whi, *wlo;
    float *sarr, *tarr;
    cudaGetSymbolAddress((void**)&xs,  g_xs);
    cudaGetSymbolAddress((void**)&qb,  g_q);
    cudaGetSymbolAddress((void**)&kb,  g_k);
    cudaGetSymbolAddress((void**)&vb,  g_v);
    cudaGetSymbolAddress((void**)&ab,  g_a);
    cudaGetSymbolAddress((void**)&whi, g_whi);
    cudaGetSymbolAddress((void**)&wlo, g_wlo);
    cudaGetSymbolAddress((void**)&sarr, g_s);
    cudaGetSymbolAddress((void**)&tarr, g_t);

    cudaFuncSetAttribute(gemm_hmma, cudaFuncAttributeMaxDynamicSharedMemorySize, SMEM_GEMM);

    for (int p = 0; p < 4; ++p) {
        prep_params<<<1, 384>>>((const float*)d_in[2 + p * 5], (const float*)d_in[3 + p * 5],
                                (const float*)d_in[4 + p * 5], (const float*)d_in[5 + p * 5],
                                sarr + p * Cc, tarr + p * Cc);
        split_w<<<(WSZ + 255) / 256, 256>>>((const float*)d_in[1 + p * 5],
                                            whi + p * WSZ, wlo + p * WSZ);
    }

    const int n4 = Bq * Cc * Nn / 4;
    spike_x_kernel<<<(n4 + 255) / 256, 256>>>(x, xs, n4);

    // fused QKV: stacked M = 1152
    gemm_hmma<<<dim3(Nn / 256, 9, Bq), 256, SMEM_GEMM>>>(
        whi, wlo, xs, qb, kb, vb, nullptr, sarr, tarr, 0, 0);

    zero_kv_kernel<<<(Bq * HEADS * HD * HD + 255) / 256, 256>>>();
    kv_kernel<<<dim3(8, HEADS, Bq), 256>>>();
    attn_kernel<<<dim3(Nn / 256, HEADS, Bq), 256>>>();

    // final P stage: mbase = 1152, fp32 direct to d_out
    gemm_hmma<<<dim3(Nn / 256, 3, Bq), 256, SMEM_GEMM>>>(
        whi, wlo, ab, nullptr, nullptr, nullptr, (float*)d_out, sarr, tarr, 3 * Cc, 1);
}

// round 7
// speedup vs baseline: 4.2838x; 1.1929x over previous
#include <cuda_runtime.h>
#include <cuda_bf16.h>
#include <math.h>
#include <stdint.h>

#define Bq    8
#define Cc    384
#define Nn    4096
#define HEADS 8
#define HD    48
#define WSZ   (Cc*Cc)

// ---------------- scratch (device globals) ----------------
__device__ __nv_bfloat16 g_xs[(size_t)Bq*Cc*Nn];   // spike(x)  [b][c][n]
__device__ __nv_bfloat16 g_q [(size_t)Bq*Cc*Nn];   // spike-q bf16 (for attn)
__device__ int8_t        g_ki8[(size_t)Bq*Cc*Nn];  // 4*spike-k int (0..4)
__device__ int8_t        g_vi8[(size_t)Bq*Cc*Nn];
__device__ __nv_bfloat16 g_a [(size_t)Bq*Cc*Nn];
__device__ __nv_bfloat16 g_whi[4*WSZ];             // stacked rows: [1536][384]
__device__ __nv_bfloat16 g_wlo[4*WSZ];
__device__ int   g_kvi[Bq*HEADS*HD*HD];            // exact integer kv sums (16x)
__device__ float g_s [4*Cc];
__device__ float g_t [4*Cc];

__device__ __forceinline__ float spikef(float x) {
    return rintf(fminf(fmaxf(x, 0.0f), 4.0f)) * 0.25f;
}

// ---------------- PTX helpers (sm_80-class ISA, compiles on plain sm_103) ----
__device__ __forceinline__ uint32_t smem_u32(const void* p) {
    uint32_t a;
    asm("{ .reg .u64 t; cvta.to.shared.u64 t, %1; cvt.u32.u64 %0, t; }" : "=r"(a) : "l"(p));
    return a;
}
__device__ __forceinline__ void cp16(uint32_t s, const void* g) {
    asm volatile("cp.async.cg.shared.global [%0], [%1], 16;" :: "r"(s), "l"(g));
}
__device__ __forceinline__ void ldsm4(uint32_t* r, uint32_t a) {
    asm volatile("ldmatrix.sync.aligned.m8n8.x4.shared.b16 {%0,%1,%2,%3}, [%4];"
        : "=r"(r[0]), "=r"(r[1]), "=r"(r[2]), "=r"(r[3]) : "r"(a));
}
__device__ __forceinline__ void ldsm4t(uint32_t* r, uint32_t a) {
    asm volatile("ldmatrix.sync.aligned.m8n8.x4.trans.shared.b16 {%0,%1,%2,%3}, [%4];"
        : "=r"(r[0]), "=r"(r[1]), "=r"(r[2]), "=r"(r[3]) : "r"(a));
}
__device__ __forceinline__ void mma16816(float* d, const uint32_t* a, const uint32_t* b) {
    asm volatile(
        "mma.sync.aligned.m16n8k16.row.col.f32.bf16.bf16.f32 "
        "{%0,%1,%2,%3}, {%4,%5,%6,%7}, {%8,%9}, {%0,%1,%2,%3};"
        : "+f"(d[0]), "+f"(d[1]), "+f"(d[2]), "+f"(d[3])
        : "r"(a[0]), "r"(a[1]), "r"(a[2]), "r"(a[3]), "r"(b[0]), "r"(b[1]));
}
__device__ __forceinline__ int dp4a_s(int a, int b, int c) {
    asm("dp4a.s32.s32 %0, %1, %2, %3;" : "=r"(c) : "r"(a), "r"(b), "r"(c));
    return c;
}

// ---------------- fused prep: BN params (all 4 stages) + zero kv -------------
__global__ void params_zero(
    const float* g0, const float* b0, const float* m0, const float* v0,
    const float* g1, const float* b1, const float* m1, const float* v1,
    const float* g2, const float* b2, const float* m2, const float* v2,
    const float* g3, const float* b3, const float* m3, const float* v3,
    float* __restrict__ s, float* __restrict__ t)
{
    const int bx = blockIdx.x, i = threadIdx.x;
    if (bx < 4) {
        const float* ga = bx == 0 ? g0 : bx == 1 ? g1 : bx == 2 ? g2 : g3;
        const float* be = bx == 0 ? b0 : bx == 1 ? b1 : bx == 2 ? b2 : b3;
        const float* me = bx == 0 ? m0 : bx == 1 ? m1 : bx == 2 ? m2 : m3;
        const float* va = bx == 0 ? v0 : bx == 1 ? v1 : bx == 2 ? v2 : v3;
        if (i < Cc) {
            float sv = ga[i] / sqrtf(va[i] + 1e-5f);
            s[bx * Cc + i] = sv;
            t[bx * Cc + i] = be[i] - me[i] * sv;
        }
    } else {
        const int q = bx - 4;                      // 4 zero blocks
        int* kv = g_kvi + q * (Bq * HEADS * HD * HD / 4);
        for (int j = i; j < Bq * HEADS * HD * HD / 4; j += 384) kv[j] = 0;
    }
}

// ---------------- fused weight split over all 4 stages -----------------------
__global__ void split_w_all(const float* __restrict__ w0, const float* __restrict__ w1,
                            const float* __restrict__ w2, const float* __restrict__ w3,
                            __nv_bfloat16* __restrict__ hi, __nv_bfloat16* __restrict__ lo) {
    const int p = blockIdx.y;
    const float* w = p == 0 ? w0 : p == 1 ? w1 : p == 2 ? w2 : w3;
    int i = blockIdx.x * 256 + threadIdx.x;
    if (i < WSZ) {
        float v = w[i];
        __nv_bfloat16 h = __float2bfloat16(v);
        hi[p * WSZ + i] = h;
        lo[p * WSZ + i] = __float2bfloat16(v - __bfloat162float(h));
    }
}

__global__ void spike_x_kernel(const float* __restrict__ x, __nv_bfloat16* __restrict__ y, int n4) {
    int i = blockIdx.x * 256 + threadIdx.x;
    if (i < n4) {
        float4 v = reinterpret_cast<const float4*>(x)[i];
        __nv_bfloat162 a = __floats2bfloat162_rn(spikef(v.x), spikef(v.y));
        __nv_bfloat162 b = __floats2bfloat162_rn(spikef(v.z), spikef(v.w));
        uint2 pk;
        pk.x = *reinterpret_cast<uint32_t*>(&a);
        pk.y = *reinterpret_cast<uint32_t*>(&b);
        reinterpret_cast<uint2*>(y)[i] = pk;
    }
}

// ---------------- HMMA GEMM, block 128m x 256n, warp 64x64, k-chunk 32 -------
// mode 0: spike(BN(.)): stage q -> bf16 [c][n]; stages k,v -> int8 (4x) [c][n]
// mode 1: BN(.) -> fp32 [c][n] direct (final output)
#define STG_B 32768
#define SMEM_GEMM 65536

__global__ __launch_bounds__(256)
void gemm_hmma(const __nv_bfloat16* __restrict__ Whi, const __nv_bfloat16* __restrict__ Wlo,
               const __nv_bfloat16* __restrict__ X,
               __nv_bfloat16* __restrict__ oq, int8_t* __restrict__ ok8,
               int8_t* __restrict__ ov8, float* __restrict__ ofp,
               const float* __restrict__ sArr, const float* __restrict__ tArr,
               int mbase, int mode)
{
    extern __shared__ char smem[];
    const uint32_t sb = smem_u32(smem);
    const int tid = threadIdx.x, lane = tid & 31, wid = tid >> 5;
    const int wm = wid & 1, wn = wid >> 1;
    const int n0 = blockIdx.x * 256, m0 = mbase + blockIdx.y * 128, b = blockIdx.z;
    const __nv_bfloat16* Xb = X + (size_t)b * (Cc * Nn);

    float acc[4][8][4];
    #pragma unroll
    for (int t = 0; t < 4; ++t)
        #pragma unroll
        for (int j = 0; j < 8; ++j)
            #pragma unroll
            for (int e = 0; e < 4; ++e) acc[t][j][e] = 0.0f;

    auto load_chunk = [&](int kc, int st) {
        uint32_t base = sb + st * STG_B;
        #pragma unroll
        for (int p = 0; p < 2; ++p) {
            int idx = tid + p * 256;
            int row = idx >> 2, c = idx & 3;
            uint32_t so = row * 64 + ((c ^ ((row >> 1) & 3)) << 4);
            cp16(base + so, Whi + (size_t)(m0 + row) * Cc + kc * 32 + c * 8);
            cp16(base + 8192 + so, Wlo + (size_t)(m0 + row) * Cc + kc * 32 + c * 8);
        }
        #pragma unroll
        for (int p = 0; p < 4; ++p) {
            int idx = tid + p * 256;
            int kr = idx >> 5, c = idx & 31;
            uint32_t so = kr * 512 + (((c & 24) | ((c & 7) ^ (kr & 7))) << 4);
            cp16(base + 16384 + so, Xb + (size_t)(kc * 32 + kr) * Nn + n0 + c * 8);
        }
        asm volatile("cp.async.commit_group;");
    };

    load_chunk(0, 0);
    const int sel = lane >> 3, l7 = lane & 7;

    for (int kc = 0; kc < 12; ++kc) {
        if (kc + 1 < 12) {
            load_chunk(kc + 1, (kc + 1) & 1);
            asm volatile("cp.async.wait_group 1;");
        } else {
            asm volatile("cp.async.wait_group 0;");
        }
        __syncthreads();

        uint32_t base = sb + (kc & 1) * STG_B;

        #pragma unroll
        for (int h = 0; h < 2; ++h) {
            uint32_t ahi[4][4], alo[4][4], bb[4][4];
            #pragma unroll
            for (int t = 0; t < 4; ++t) {
                int row = wm * 64 + t * 16 + (sel & 1) * 8 + l7;
                int kcx = h * 2 + (sel >> 1);
                uint32_t ad = base + row * 64 + ((kcx ^ ((row >> 1) & 3)) << 4);
                ldsm4(ahi[t], ad);
                ldsm4(alo[t], ad + 8192);
            }
            #pragma unroll
            for (int j = 0; j < 4; ++j) {
                int kr = h * 16 + (sel & 1) * 8 + l7;
                int nc = (wn * 64 + j * 16 + (sel >> 1) * 8) >> 3;
                uint32_t bd = base + 16384 + kr * 512 +
                              (((nc & 24) | ((nc & 7) ^ (kr & 7))) << 4);
                ldsm4t(bb[j], bd);
            }
            #pragma unroll
            for (int t = 0; t < 4; ++t)
                #pragma unroll
                for (int j = 0; j < 8; ++j) {
                    const uint32_t* bf = &bb[j >> 1][(j & 1) * 2];
                    mma16816(acc[t][j], ahi[t], bf);
                    mma16816(acc[t][j], alo[t], bf);
                }
        }
        __syncthreads();
    }

    if (mode == 0) {
        const int st = m0 / Cc;                      // 0=q, 1=k, 2=v
        const int mloc = m0 - st * Cc;
        __nv_bfloat16* sm = reinterpret_cast<__nv_bfloat16*>(smem);
        #pragma unroll
        for (int p = 0; p < 2; ++p) {
            if ((wn >> 1) == p) {
                #pragma unroll
                for (int t = 0; t < 4; ++t) {
                    int r0 = wm * 64 + t * 16 + (lane >> 2);
                    float s0 = sArr[m0 + r0], t0 = tArr[m0 + r0];
                    float s1 = sArr[m0 + r0 + 8], t1 = tArr[m0 + r0 + 8];
                    #pragma unroll
                    for (int j = 0; j < 8; ++j) {
                        int col = (wn & 1) * 64 + j * 8 + 2 * (lane & 3);
                        __nv_bfloat162 p0 = __floats2bfloat162_rn(
                            spikef(acc[t][j][0] * s0 + t0), spikef(acc[t][j][1] * s0 + t0));
                        __nv_bfloat162 p1 = __floats2bfloat162_rn(
                            spikef(acc[t][j][2] * s1 + t1), spikef(acc[t][j][3] * s1 + t1));
                        *reinterpret_cast<__nv_bfloat162*>(sm + r0 * 136 + col) = p0;
                        *reinterpret_cast<__nv_bfloat162*>(sm + (r0 + 8) * 136 + col) = p1;
                    }
                }
            }
            __syncthreads();
            if (st == 0) {
                __nv_bfloat16* Yb = oq + (size_t)b * (Cc * Nn);
                #pragma unroll
                for (int it = 0; it < 8; ++it) {
                    int idx = tid + it * 256;
                    int row = idx >> 4, ci = idx & 15;
                    uint4 u4 = *reinterpret_cast<const uint4*>(sm + row * 136 + ci * 8);
                    *reinterpret_cast<uint4*>(
                        Yb + (size_t)(mloc + row) * Nn + n0 + p * 128 + ci * 8) = u4;
                }
            } else {
                int8_t* Yb = (st == 1 ? ok8 : ov8) + (size_t)b * (Cc * Nn);
                #pragma unroll
                for (int it = 0; it < 8; ++it) {
                    int idx = tid + it * 256;
                    int row = idx >> 4, ci = idx & 15;
                    uint4 u4 = *reinterpret_cast<const uint4*>(sm + row * 136 + ci * 8);
                    const __nv_bfloat16* pb = reinterpret_cast<const __nv_bfloat16*>(&u4);
                    uint32_t lo = 0, hi = 0;
                    #pragma unroll
                    for (int z = 0; z < 4; ++z)
                        lo |= ((uint32_t)(int)(__bfloat162float(pb[z]) * 4.0f)) << (8 * z);
                    #pragma unroll
                    for (int z = 0; z < 4; ++z)
                        hi |= ((uint32_t)(int)(__bfloat162float(pb[4 + z]) * 4.0f)) << (8 * z);
                    uint2 pk = make_uint2(lo, hi);
                    *reinterpret_cast<uint2*>(
                        Yb + (size_t)(mloc + row) * Nn + n0 + p * 128 + ci * 8) = pk;
                }
            }
            __syncthreads();
        }
    } else {
        float* Yb = ofp + (size_t)b * (Cc * Nn);
        const int mloc = m0 - 3 * Cc;
        #pragma unroll
        for (int t = 0; t < 4; ++t) {
            int r0 = wm * 64 + t * 16 + (lane >> 2);
            float s0 = sArr[m0 + r0], t0 = tArr[m0 + r0];
            float s1 = sArr[m0 + r0 + 8], t1 = tArr[m0 + r0 + 8];
            #pragma unroll
            for (int j = 0; j < 8; ++j) {
                int col = n0 + wn * 64 + j * 8 + 2 * (lane & 3);
                float2 p0 = make_float2(acc[t][j][0] * s0 + t0, acc[t][j][1] * s0 + t0);
                float2 p1 = make_float2(acc[t][j][2] * s1 + t1, acc[t][j][3] * s1 + t1);
                *reinterpret_cast<float2*>(Yb + (size_t)(mloc + r0) * Nn + col) = p0;
                *reinterpret_cast<float2*>(Yb + (size_t)(mloc + r0 + 8) * Nn + col) = p1;
            }
        }
    }
}

// ---------------- kv via dp4a: kv[b,h,d,e] = sum_n 4k*4v (exact s32) ---------
__global__ __launch_bounds__(256)
void kv_kernel() {
    const int chunk = blockIdx.x, h = blockIdx.y, b = blockIdx.z;
    const int* kp = reinterpret_cast<const int*>(
        g_ki8 + ((size_t)b * Cc + h * HD) * Nn) + chunk * 128;
    const int* vp = reinterpret_cast<const int*>(
        g_vi8 + ((size_t)b * Cc + h * HD) * Nn) + chunk * 128;

    __shared__ int ks[64][49];   // [word][d], pad 49 -> conflict-free
    __shared__ int vs[64][49];

    const int tid = threadIdx.x;
    const int te = tid & 15, td = tid >> 4;
    int acc[3][3] = {};

    #pragma unroll
    for (int sub = 0; sub < 2; ++sub) {
        #pragma unroll
        for (int p = 0; p < 12; ++p) {
            int i = tid + p * 256;
            int d = i >> 6, w = i & 63;
            ks[w][d] = kp[(size_t)d * (Nn / 4) + sub * 64 + w];
            vs[w][d] = vp[(size_t)d * (Nn / 4) + sub * 64 + w];
        }
        __syncthreads();
        #pragma unroll 4
        for (int w = 0; w < 64; ++w) {
            int kd[3], ve[3];
            #pragma unroll
            for (int i = 0; i < 3; ++i) kd[i] = ks[w][td * 3 + i];
            #pragma unroll
            for (int i = 0; i < 3; ++i) ve[i] = vs[w][te * 3 + i];
            #pragma unroll
            for (int i = 0; i < 3; ++i)
                #pragma unroll
                for (int j = 0; j < 3; ++j)
                    acc[i][j] = dp4a_s(kd[i], ve[j], acc[i][j]);
        }
        __syncthreads();
    }
    int* kvp = g_kvi + (size_t)(b * HEADS + h) * HD * HD;
    #pragma unroll
    for (int i = 0; i < 3; ++i)
        #pragma unroll
        for (int j = 0; j < 3; ++j)
            atomicAdd(&kvp[(td * 3 + i) * HD + te * 3 + j], acc[i][j]);
}

// ---------------- attn: a[h*48+e, n] = spike((mult/16) * sum_d q[d,n]*kvi) ---
__global__ __launch_bounds__(256)
void attn_kernel() {
    const int n = blockIdx.x * 256 + threadIdx.x;
    const int h = blockIdx.y, b = blockIdx.z;

    __shared__ float4 kv4[HD][12];
    const int* kvp = g_kvi + (size_t)(b * HEADS + h) * HD * HD;
    for (int i = threadIdx.x; i < HD * 12; i += 256) {
        int4 iv = reinterpret_cast<const int4*>(kvp)[i];
        reinterpret_cast<float4*>(kv4)[i] =
            make_float4((float)iv.x, (float)iv.y, (float)iv.z, (float)iv.w);
    }
    __syncthreads();

    const __nv_bfloat16* qp = g_q + ((size_t)b * Cc + h * HD) * Nn + n;
    float qr[HD];
    #pragma unroll
    for (int d = 0; d < HD; ++d) qr[d] = __bfloat162float(qp[(size_t)d * Nn]);

    float4 accv[12];
    #pragma unroll
    for (int e = 0; e < 12; ++e) accv[e] = make_float4(0.f, 0.f, 0.f, 0.f);
    #pragma unroll
    for (int d = 0; d < HD; ++d) {
        float qd = qr[d];
        #pragma unroll
        for (int e = 0; e < 12; ++e) {
            float4 kk = kv4[d][e];
            accv[e].x = fmaf(qd, kk.x, accv[e].x);
            accv[e].y = fmaf(qd, kk.y, accv[e].y);
            accv[e].z = fmaf(qd, kk.z, accv[e].z);
            accv[e].w = fmaf(qd, kk.w, accv[e].w);
        }
    }

    __nv_bfloat16* ap = g_a + ((size_t)b * Cc + h * HD) * Nn + n;
    const float mult16 = 0.28867513459481287f * 0.0625f;   // (2/sqrt(48)) / 16
    #pragma unroll
    for (int e = 0; e < 12; ++e) {
        ap[(size_t)(e * 4 + 0) * Nn] = __float2bfloat16(spikef(accv[e].x * mult16));
        ap[(size_t)(e * 4 + 1) * Nn] = __float2bfloat16(spikef(accv[e].y * mult16));
        ap[(size_t)(e * 4 + 2) * Nn] = __float2bfloat16(spikef(accv[e].z * mult16));
        ap[(size_t)(e * 4 + 3) * Nn] = __float2bfloat16(spikef(accv[e].w * mult16));
    }
}

// ---------------- launch ----------------
extern "C" void kernel_launch(void* const* d_in, const int* in_sizes, int n_in,
                              void* d_out, int out_size) {
    const float* x = (const float*)d_in[0];
    __nv_bfloat16 *xs, *qb, *ab, *whi, *wlo;
    int8_t *k8, *v8;
    float *sarr, *tarr;
    cudaGetSymbolAddress((void**)&xs,  g_xs);
    cudaGetSymbolAddress((void**)&qb,  g_q);
    cudaGetSymbolAddress((void**)&k8,  g_ki8);
    cudaGetSymbolAddress((void**)&v8,  g_vi8);
    cudaGetSymbolAddress((void**)&ab,  g_a);
    cudaGetSymbolAddress((void**)&whi, g_whi);
    cudaGetSymbolAddress((void**)&wlo, g_wlo);
    cudaGetSymbolAddress((void**)&sarr, g_s);
    cudaGetSymbolAddress((void**)&tarr, g_t);

    cudaFuncSetAttribute(gemm_hmma, cudaFuncAttributeMaxDynamicSharedMemorySize, SMEM_GEMM);

    params_zero<<<8, 384>>>(
        (const float*)d_in[2],  (const float*)d_in[3],  (const float*)d_in[4],  (const float*)d_in[5],
        (const float*)d_in[7],  (const float*)d_in[8],  (const float*)d_in[9],  (const float*)d_in[10],
        (const float*)d_in[12], (const float*)d_in[13], (const float*)d_in[14], (const float*)d_in[15],
        (const float*)d_in[17], (const float*)d_in[18], (const float*)d_in[19], (const float*)d_in[20],
        sarr, tarr);
    split_w_all<<<dim3((WSZ + 255) / 256, 4), 256>>>(
        (const float*)d_in[1], (const float*)d_in[6],
        (const float*)d_in[11], (const float*)d_in[16], whi, wlo);

    const int n4 = Bq * Cc * Nn / 4;
    spike_x_kernel<<<(n4 + 255) / 256, 256>>>(x, xs, n4);

    // fused QKV: stacked M = 1152
    gemm_hmma<<<dim3(Nn / 256, 9, Bq), 256, SMEM_GEMM>>>(
        whi, wlo, xs, qb, k8, v8, nullptr, sarr, tarr, 0, 0);

    kv_kernel<<<dim3(8, HEADS, Bq), 256>>>();
    attn_kernel<<<dim3(Nn / 256, HEADS, Bq), 256>>>();

    gemm_hmma<<<dim3(Nn / 256, 3, Bq), 256, SMEM_GEMM>>>(
        whi, wlo, ab, nullptr, nullptr, nullptr, (float*)d_out, sarr, tarr, 3 * Cc, 1);
}

// round 8
// speedup vs baseline: 4.8518x; 1.1326x over previous
#include <cuda_runtime.h>
#include <cuda_bf16.h>
#include <math.h>
#include <stdint.h>

#define Bq    8
#define Cc    384
#define Nn    4096
#define HEADS 8
#define HD    48
#define WSZ   (Cc*Cc)

// ---------------- scratch (device globals) ----------------
__device__ __nv_bfloat16 g_xs[(size_t)Bq*Cc*Nn];   // spike(x)  [b][c][n]
__device__ __nv_bfloat16 g_q [(size_t)Bq*Cc*Nn];   // spike-q bf16 (for attn)
__device__ int8_t        g_ki8[(size_t)Bq*Cc*Nn];  // 4*spike-k int (0..4)
__device__ int8_t        g_vi8[(size_t)Bq*Cc*Nn];
__device__ __nv_bfloat16 g_a [(size_t)Bq*Cc*Nn];
__device__ __nv_bfloat16 g_whi[4*WSZ];             // stacked rows: [1536][384]
__device__ __nv_bfloat16 g_wlo[4*WSZ];
__device__ int   g_kvi[Bq*HEADS*HD*HD];            // exact integer kv sums (16x)
__device__ float g_s [4*Cc];
__device__ float g_t [4*Cc];

__device__ __forceinline__ float spikef(float x) {
    return rintf(fminf(fmaxf(x, 0.0f), 4.0f)) * 0.25f;
}

// ---------------- PTX helpers (sm_80-class ISA, compiles on plain sm_103) ----
__device__ __forceinline__ uint32_t smem_u32(const void* p) {
    uint32_t a;
    asm("{ .reg .u64 t; cvta.to.shared.u64 t, %1; cvt.u32.u64 %0, t; }" : "=r"(a) : "l"(p));
    return a;
}
__device__ __forceinline__ void cp16(uint32_t s, const void* g) {
    asm volatile("cp.async.cg.shared.global [%0], [%1], 16;" :: "r"(s), "l"(g));
}
__device__ __forceinline__ void ldsm4(uint32_t* r, uint32_t a) {
    asm volatile("ldmatrix.sync.aligned.m8n8.x4.shared.b16 {%0,%1,%2,%3}, [%4];"
        : "=r"(r[0]), "=r"(r[1]), "=r"(r[2]), "=r"(r[3]) : "r"(a));
}
__device__ __forceinline__ void ldsm4t(uint32_t* r, uint32_t a) {
    asm volatile("ldmatrix.sync.aligned.m8n8.x4.trans.shared.b16 {%0,%1,%2,%3}, [%4];"
        : "=r"(r[0]), "=r"(r[1]), "=r"(r[2]), "=r"(r[3]) : "r"(a));
}
__device__ __forceinline__ void mma16816(float* d, const uint32_t* a, const uint32_t* b) {
    asm volatile(
        "mma.sync.aligned.m16n8k16.row.col.f32.bf16.bf16.f32 "
        "{%0,%1,%2,%3}, {%4,%5,%6,%7}, {%8,%9}, {%0,%1,%2,%3};"
        : "+f"(d[0]), "+f"(d[1]), "+f"(d[2]), "+f"(d[3])
        : "r"(a[0]), "r"(a[1]), "r"(a[2]), "r"(a[3]), "r"(b[0]), "r"(b[1]));
}
__device__ __forceinline__ int dp4a_s(int a, int b, int c) {
    asm("dp4a.s32.s32 %0, %1, %2, %3;" : "=r"(c) : "r"(a), "r"(b), "r"(c));
    return c;
}

// ---------------- fused prep: BN params (all 4 stages) + zero kv -------------
__global__ void params_zero(
    const float* g0, const float* b0, const float* m0, const float* v0,
    const float* g1, const float* b1, const float* m1, const float* v1,
    const float* g2, const float* b2, const float* m2, const float* v2,
    const float* g3, const float* b3, const float* m3, const float* v3,
    float* __restrict__ s, float* __restrict__ t)
{
    const int bx = blockIdx.x, i = threadIdx.x;
    if (bx < 4) {
        const float* ga = bx == 0 ? g0 : bx == 1 ? g1 : bx == 2 ? g2 : g3;
        const float* be = bx == 0 ? b0 : bx == 1 ? b1 : bx == 2 ? b2 : b3;
        const float* me = bx == 0 ? m0 : bx == 1 ? m1 : bx == 2 ? m2 : m3;
        const float* va = bx == 0 ? v0 : bx == 1 ? v1 : bx == 2 ? v2 : v3;
        if (i < Cc) {
            float sv = ga[i] / sqrtf(va[i] + 1e-5f);
            s[bx * Cc + i] = sv;
            t[bx * Cc + i] = be[i] - me[i] * sv;
        }
    } else {
        const int q = bx - 4;
        int* kv = g_kvi + q * (Bq * HEADS * HD * HD / 4);
        for (int j = i; j < Bq * HEADS * HD * HD / 4; j += 384) kv[j] = 0;
    }
}

// ---------------- fused weight split over all 4 stages -----------------------
__global__ void split_w_all(const float* __restrict__ w0, const float* __restrict__ w1,
                            const float* __restrict__ w2, const float* __restrict__ w3,
                            __nv_bfloat16* __restrict__ hi, __nv_bfloat16* __restrict__ lo) {
    const int p = blockIdx.y;
    const float* w = p == 0 ? w0 : p == 1 ? w1 : p == 2 ? w2 : w3;
    int i = blockIdx.x * 256 + threadIdx.x;
    if (i < WSZ) {
        float v = w[i];
        __nv_bfloat16 h = __float2bfloat16(v);
        hi[p * WSZ + i] = h;
        lo[p * WSZ + i] = __float2bfloat16(v - __bfloat162float(h));
    }
}

__global__ void spike_x_kernel(const float* __restrict__ x, __nv_bfloat16* __restrict__ y, int n4) {
    int i = blockIdx.x * 256 + threadIdx.x;
    if (i < n4) {
        float4 v = reinterpret_cast<const float4*>(x)[i];
        __nv_bfloat162 a = __floats2bfloat162_rn(spikef(v.x), spikef(v.y));
        __nv_bfloat162 b = __floats2bfloat162_rn(spikef(v.z), spikef(v.w));
        uint2 pk;
        pk.x = *reinterpret_cast<uint32_t*>(&a);
        pk.y = *reinterpret_cast<uint32_t*>(&b);
        reinterpret_cast<uint2*>(y)[i] = pk;
    }
}

// ---------------- HMMA GEMM, block 128m x 128n, warp 64x32, 2 CTAs/SM --------
// mode 0: spike(BN(.)): stage q -> bf16 [c][n]; stages k,v -> int8 (4x) [c][n]
// mode 1: BN(.) -> fp32 [c][n] direct (final output)
#define STG_B 24576            // per stage: A_hi 8K | A_lo 8K | B 8K
#define SMEM_GEMM 49152

__global__ __launch_bounds__(256, 2)
void gemm_hmma(const __nv_bfloat16* __restrict__ Whi, const __nv_bfloat16* __restrict__ Wlo,
               const __nv_bfloat16* __restrict__ X,
               __nv_bfloat16* __restrict__ oq, int8_t* __restrict__ ok8,
               int8_t* __restrict__ ov8, float* __restrict__ ofp,
               const float* __restrict__ sArr, const float* __restrict__ tArr,
               int mbase, int mode)
{
    extern __shared__ char smem[];
    const uint32_t sb = smem_u32(smem);
    const int tid = threadIdx.x, lane = tid & 31, wid = tid >> 5;
    const int wm = wid & 1, wn = wid >> 1;
    const int n0 = blockIdx.x * 128, m0 = mbase + blockIdx.y * 128, b = blockIdx.z;
    const __nv_bfloat16* Xb = X + (size_t)b * (Cc * Nn);

    float acc[4][4][4];
    #pragma unroll
    for (int t = 0; t < 4; ++t)
        #pragma unroll
        for (int u = 0; u < 4; ++u)
            #pragma unroll
            for (int e = 0; e < 4; ++e) acc[t][u][e] = 0.0f;

    auto load_chunk = [&](int kc, int st) {
        uint32_t base = sb + st * STG_B;
        #pragma unroll
        for (int p = 0; p < 2; ++p) {                   // A: 128 rows x 4 chunks
            int idx = tid + p * 256;
            int row = idx >> 2, c = idx & 3;
            uint32_t so = row * 64 + ((c ^ ((row >> 1) & 3)) << 4);
            cp16(base + so, Whi + (size_t)(m0 + row) * Cc + kc * 32 + c * 8);
            cp16(base + 8192 + so, Wlo + (size_t)(m0 + row) * Cc + kc * 32 + c * 8);
        }
        #pragma unroll
        for (int p = 0; p < 2; ++p) {                   // B: 32 k-rows x 16 chunks
            int idx = tid + p * 256;
            int kr = idx >> 4, c = idx & 15;
            uint32_t so = kr * 256 + (((c & 8) | ((c & 7) ^ (kr & 7))) << 4);
            cp16(base + 16384 + so, Xb + (size_t)(kc * 32 + kr) * Nn + n0 + c * 8);
        }
        asm volatile("cp.async.commit_group;");
    };

    load_chunk(0, 0);
    const int sel = lane >> 3, l7 = lane & 7;

    for (int kc = 0; kc < 12; ++kc) {
        if (kc + 1 < 12) {
            load_chunk(kc + 1, (kc + 1) & 1);
            asm volatile("cp.async.wait_group 1;");
        } else {
            asm volatile("cp.async.wait_group 0;");
        }
        __syncthreads();

        uint32_t base = sb + (kc & 1) * STG_B;

        #pragma unroll
        for (int h = 0; h < 2; ++h) {
            uint32_t bb[2][4];
            #pragma unroll
            for (int j = 0; j < 2; ++j) {
                int kr = h * 16 + (sel & 1) * 8 + l7;
                int nc = (wn * 32 + j * 16 + (sel >> 1) * 8) >> 3;
                uint32_t bd = base + 16384 + kr * 256 +
                              (((nc & 8) | ((nc & 7) ^ (kr & 7))) << 4);
                ldsm4t(bb[j], bd);
            }
            #pragma unroll
            for (int t = 0; t < 4; ++t) {
                int row = wm * 64 + t * 16 + (sel & 1) * 8 + l7;
                int kcx = h * 2 + (sel >> 1);
                uint32_t ad = base + row * 64 + ((kcx ^ ((row >> 1) & 3)) << 4);
                uint32_t ahi[4], alo[4];
                ldsm4(ahi, ad);
                #pragma unroll
                for (int u = 0; u < 4; ++u)
                    mma16816(acc[t][u], ahi, &bb[u >> 1][(u & 1) * 2]);
                ldsm4(alo, ad + 8192);
                #pragma unroll
                for (int u = 0; u < 4; ++u)
                    mma16816(acc[t][u], alo, &bb[u >> 1][(u & 1) * 2]);
            }
        }
        __syncthreads();
    }

    if (mode == 0) {
        const int st = m0 / Cc;                      // 0=q, 1=k, 2=v
        const int mloc = m0 - st * Cc;
        __nv_bfloat16* sm = reinterpret_cast<__nv_bfloat16*>(smem);
        #pragma unroll
        for (int t = 0; t < 4; ++t) {
            int r0 = wm * 64 + t * 16 + (lane >> 2);
            float s0 = sArr[m0 + r0], t0 = tArr[m0 + r0];
            float s1 = sArr[m0 + r0 + 8], t1 = tArr[m0 + r0 + 8];
            #pragma unroll
            for (int u = 0; u < 4; ++u) {
                int col = wn * 32 + u * 8 + 2 * (lane & 3);
                __nv_bfloat162 p0 = __floats2bfloat162_rn(
                    spikef(acc[t][u][0] * s0 + t0), spikef(acc[t][u][1] * s0 + t0));
                __nv_bfloat162 p1 = __floats2bfloat162_rn(
                    spikef(acc[t][u][2] * s1 + t1), spikef(acc[t][u][3] * s1 + t1));
                *reinterpret_cast<__nv_bfloat162*>(sm + r0 * 136 + col) = p0;
                *reinterpret_cast<__nv_bfloat162*>(sm + (r0 + 8) * 136 + col) = p1;
            }
        }
        __syncthreads();
        if (st == 0) {
            __nv_bfloat16* Yb = oq + (size_t)b * (Cc * Nn);
            #pragma unroll
            for (int it = 0; it < 8; ++it) {
                int idx = tid + it * 256;
                int row = idx >> 4, ci = idx & 15;
                uint4 u4 = *reinterpret_cast<const uint4*>(sm + row * 136 + ci * 8);
                *reinterpret_cast<uint4*>(
                    Yb + (size_t)(mloc + row) * Nn + n0 + ci * 8) = u4;
            }
        } else {
            int8_t* Yb = (st == 1 ? ok8 : ov8) + (size_t)b * (Cc * Nn);
            #pragma unroll
            for (int it = 0; it < 8; ++it) {
                int idx = tid + it * 256;
                int row = idx >> 4, ci = idx & 15;
                uint4 u4 = *reinterpret_cast<const uint4*>(sm + row * 136 + ci * 8);
                const __nv_bfloat16* pb = reinterpret_cast<const __nv_bfloat16*>(&u4);
                uint32_t lo = 0, hi = 0;
                #pragma unroll
                for (int z = 0; z < 4; ++z)
                    lo |= ((uint32_t)(int)(__bfloat162float(pb[z]) * 4.0f)) << (8 * z);
                #pragma unroll
                for (int z = 0; z < 4; ++z)
                    hi |= ((uint32_t)(int)(__bfloat162float(pb[4 + z]) * 4.0f)) << (8 * z);
                uint2 pk = make_uint2(lo, hi);
                *reinterpret_cast<uint2*>(
                    Yb + (size_t)(mloc + row) * Nn + n0 + ci * 8) = pk;
            }
        }
    } else {
        float* Yb = ofp + (size_t)b * (Cc * Nn);
        const int mloc = m0 - 3 * Cc;
        #pragma unroll
        for (int t = 0; t < 4; ++t) {
            int r0 = wm * 64 + t * 16 + (lane >> 2);
            float s0 = sArr[m0 + r0], t0 = tArr[m0 + r0];
            float s1 = sArr[m0 + r0 + 8], t1 = tArr[m0 + r0 + 8];
            #pragma unroll
            for (int u = 0; u < 4; ++u) {
                int col = n0 + wn * 32 + u * 8 + 2 * (lane & 3);
                float2 p0 = make_float2(acc[t][u][0] * s0 + t0, acc[t][u][1] * s0 + t0);
                float2 p1 = make_float2(acc[t][u][2] * s1 + t1, acc[t][u][3] * s1 + t1);
                *reinterpret_cast<float2*>(Yb + (size_t)(mloc + r0) * Nn + col) = p0;
                *reinterpret_cast<float2*>(Yb + (size_t)(mloc + r0 + 8) * Nn + col) = p1;
            }
        }
    }
}

// ---------------- kv via dp4a: kv[b,h,d,e] = sum_n 4k*4v (exact s32) ---------
__global__ __launch_bounds__(256)
void kv_kernel() {
    const int chunk = blockIdx.x, h = blockIdx.y, b = blockIdx.z;
    const int* kp = reinterpret_cast<const int*>(
        g_ki8 + ((size_t)b * Cc + h * HD) * Nn) + chunk * 128;
    const int* vp = reinterpret_cast<const int*>(
        g_vi8 + ((size_t)b * Cc + h * HD) * Nn) + chunk * 128;

    __shared__ int ks[64][49];
    __shared__ int vs[64][49];

    const int tid = threadIdx.x;
    const int te = tid & 15, td = tid >> 4;
    int acc[3][3] = {};

    #pragma unroll
    for (int sub = 0; sub < 2; ++sub) {
        #pragma unroll
        for (int p = 0; p < 12; ++p) {
            int i = tid + p * 256;
            int d = i >> 6, w = i & 63;
            ks[w][d] = kp[(size_t)d * (Nn / 4) + sub * 64 + w];
            vs[w][d] = vp[(size_t)d * (Nn / 4) + sub * 64 + w];
        }
        __syncthreads();
        #pragma unroll 4
        for (int w = 0; w < 64; ++w) {
            int kd[3], ve[3];
            #pragma unroll
            for (int i = 0; i < 3; ++i) kd[i] = ks[w][td * 3 + i];
            #pragma unroll
            for (int i = 0; i < 3; ++i) ve[i] = vs[w][te * 3 + i];
            #pragma unroll
            for (int i = 0; i < 3; ++i)
                #pragma unroll
                for (int j = 0; j < 3; ++j)
                    acc[i][j] = dp4a_s(kd[i], ve[j], acc[i][j]);
        }
        __syncthreads();
    }
    int* kvp = g_kvi + (size_t)(b * HEADS + h) * HD * HD;
    #pragma unroll
    for (int i = 0; i < 3; ++i)
        #pragma unroll
        for (int j = 0; j < 3; ++j)
            atomicAdd(&kvp[(td * 3 + i) * HD + te * 3 + j], acc[i][j]);
}

// ---------------- attn: a[h*48+e, n] = spike((mult/16) * sum_d q[d,n]*kvi) ---
__global__ __launch_bounds__(256)
void attn_kernel() {
    const int n = blockIdx.x * 256 + threadIdx.x;
    const int h = blockIdx.y, b = blockIdx.z;

    __shared__ float4 kv4[HD][12];
    const int* kvp = g_kvi + (size_t)(b * HEADS + h) * HD * HD;
    for (int i = threadIdx.x; i < HD * 12; i += 256) {
        int4 iv = reinterpret_cast<const int4*>(kvp)[i];
        reinterpret_cast<float4*>(kv4)[i] =
            make_float4((float)iv.x, (float)iv.y, (float)iv.z, (float)iv.w);
    }
    __syncthreads();

    const __nv_bfloat16* qp = g_q + ((size_t)b * Cc + h * HD) * Nn + n;
    float qr[HD];
    #pragma unroll
    for (int d = 0; d < HD; ++d) qr[d] = __bfloat162float(qp[(size_t)d * Nn]);

    float4 accv[12];
    #pragma unroll
    for (int e = 0; e < 12; ++e) accv[e] = make_float4(0.f, 0.f, 0.f, 0.f);
    #pragma unroll
    for (int d = 0; d < HD; ++d) {
        float qd = qr[d];
        #pragma unroll
        for (int e = 0; e < 12; ++e) {
            float4 kk = kv4[d][e];
            accv[e].x = fmaf(qd, kk.x, accv[e].x);
            accv[e].y = fmaf(qd, kk.y, accv[e].y);
            accv[e].z = fmaf(qd, kk.z, accv[e].z);
            accv[e].w = fmaf(qd, kk.w, accv[e].w);
        }
    }

    __nv_bfloat16* ap = g_a + ((size_t)b * Cc + h * HD) * Nn + n;
    const float mult16 = 0.28867513459481287f * 0.0625f;   // (2/sqrt(48)) / 16
    #pragma unroll
    for (int e = 0; e < 12; ++e) {
        ap[(size_t)(e * 4 + 0) * Nn] = __float2bfloat16(spikef(accv[e].x * mult16));
        ap[(size_t)(e * 4 + 1) * Nn] = __float2bfloat16(spikef(accv[e].y * mult16));
        ap[(size_t)(e * 4 + 2) * Nn] = __float2bfloat16(spikef(accv[e].z * mult16));
        ap[(size_t)(e * 4 + 3) * Nn] = __float2bfloat16(spikef(accv[e].w * mult16));
    }
}

// ---------------- launch ----------------
extern "C" void kernel_launch(void* const* d_in, const int* in_sizes, int n_in,
                              void* d_out, int out_size) {
    const float* x = (const float*)d_in[0];
    __nv_bfloat16 *xs, *qb, *ab, *whi, *wlo;
    int8_t *k8, *v8;
    float *sarr, *tarr;
    cudaGetSymbolAddress((void**)&xs,  g_xs);
    cudaGetSymbolAddress((void**)&qb,  g_q);
    cudaGetSymbolAddress((void**)&k8,  g_ki8);
    cudaGetSymbolAddress((void**)&v8,  g_vi8);
    cudaGetSymbolAddress((void**)&ab,  g_a);
    cudaGetSymbolAddress((void**)&whi, g_whi);
    cudaGetSymbolAddress((void**)&wlo, g_wlo);
    cudaGetSymbolAddress((void**)&sarr, g_s);
    cudaGetSymbolAddress((void**)&tarr, g_t);

    cudaFuncSetAttribute(gemm_hmma, cudaFuncAttributeMaxDynamicSharedMemorySize, SMEM_GEMM);

    params_zero<<<8, 384>>>(
        (const float*)d_in[2],  (const float*)d_in[3],  (const float*)d_in[4],  (const float*)d_in[5],
        (const float*)d_in[7],  (const float*)d_in[8],  (const float*)d_in[9],  (const float*)d_in[10],
        (const float*)d_in[12], (const float*)d_in[13], (const float*)d_in[14], (const float*)d_in[15],
        (const float*)d_in[17], (const float*)d_in[18], (const float*)d_in[19], (const float*)d_in[20],
        sarr, tarr);
    split_w_all<<<dim3((WSZ + 255) / 256, 4), 256>>>(
        (const float*)d_in[1], (const float*)d_in[6],
        (const float*)d_in[11], (const float*)d_in[16], whi, wlo);

    const int n4 = Bq * Cc * Nn / 4;
    spike_x_kernel<<<(n4 + 255) / 256, 256>>>(x, xs, n4);

    // fused QKV: stacked M = 1152
    gemm_hmma<<<dim3(Nn / 128, 9, Bq), 256, SMEM_GEMM>>>(
        whi, wlo, xs, qb, k8, v8, nullptr, sarr, tarr, 0, 0);

    kv_kernel<<<dim3(8, HEADS, Bq), 256>>>();
    attn_kernel<<<dim3(Nn / 256, HEADS, Bq), 256>>>();

    gemm_hmma<<<dim3(Nn / 128, 3, Bq), 256, SMEM_GEMM>>>(
        whi, wlo, ab, nullptr, nullptr, nullptr, (float*)d_out, sarr, tarr, 3 * Cc, 1);
}